// round 8
// baseline (speedup 1.0000x reference)
#include <cuda_runtime.h>
#include <cuda_fp16.h>
#include <cstdint>

// ---------------------------------------------------------------------------
// DeformRoIPooling (deformable PS-RoI pooling), GROUP_SIZE=1 specialization.
//
// data:   (B=2, C=256, H=128, W=128) f32
// rois:   (N=128, 5) f32  [b, x1, y1, x2, y2]
// offset: (N=128, 2, 7, 7) f32
// out:    (N=128, 256, 7, 7) f32
//
// R7b: fp16 scratch + branch-free flat gather, 8 channels/thread (one warp
//      per bin, LDG.128 corners) and packed f32x2 FMA accumulation to
//      minimize issued instructions (kernel is issue-bound, 68% at R6).
// ---------------------------------------------------------------------------

#define BQ   2
#define CQ   256
#define HQ   128
#define WQ   128
#define NROI 128
#define PQ   7
#define SQ   4
#define SPATIAL_SCALE 0.0625f
#define TRANS_STD 0.1f

// 16 MB transposed fp16 scratch: (B, H, W, C) — L2-resident
__device__ __half g_tdata[(size_t)BQ * HQ * WQ * CQ];

// ---------------------------------------------------------------------------
// Transpose + f32->fp16 convert: per batch, (C=256) x (P=16384) -> (P) x (C).
// ---------------------------------------------------------------------------
__global__ void __launch_bounds__(256) transpose_kernel(const float* __restrict__ src) {
    __shared__ float tile[32][68];
    const int b  = blockIdx.z;
    const int c0 = blockIdx.y * 32;
    const int p0 = blockIdx.x * 64;
    const float* s = src + ((size_t)b * CQ + c0) * (HQ * WQ) + p0;
    __half* d      = g_tdata + (size_t)b * HQ * WQ * CQ;

    const int i = threadIdx.x;
    {
        const int c = i >> 4;
        const int q = i & 15;
        #pragma unroll
        for (int r = 0; r < 2; r++) {
            float4 v = *(const float4*)(s + (size_t)(c + 16 * r) * (HQ * WQ) + 4 * q);
            *(float4*)&tile[c + 16 * r][4 * q] = v;
        }
    }
    __syncthreads();
    {
        const int p = i >> 2;               // 0..63
        const int q = i & 3;                // 0..3 -> channel group of 8
        __half2 h[4];
        #pragma unroll
        for (int k = 0; k < 4; k++) {
            float2 f;
            f.x = tile[q * 8 + 2 * k + 0][p];
            f.y = tile[q * 8 + 2 * k + 1][p];
            h[k] = __float22half2_rn(f);
        }
        *(uint4*)(d + (size_t)(p0 + p) * CQ + c0 + 8 * q) = *(const uint4*)h;
    }
}

// ---------------------------------------------------------------------------
// Packed f32x2 helpers (Blackwell FFMA2 / FMUL2 via PTX)
// ---------------------------------------------------------------------------
__device__ __forceinline__ unsigned long long pack2(float v) {
    unsigned long long r;
    asm("mov.b64 %0, {%1, %1};" : "=l"(r) : "f"(v));
    return r;
}
__device__ __forceinline__ unsigned long long mul2(unsigned long long a,
                                                   unsigned long long b) {
    unsigned long long r;
    asm("mul.rn.f32x2 %0, %1, %2;" : "=l"(r) : "l"(a), "l"(b));
    return r;
}
__device__ __forceinline__ void fma2(unsigned long long& d,
                                     unsigned long long a,
                                     unsigned long long b) {
    asm("fma.rn.f32x2 %0, %1, %2, %0;" : "+l"(d) : "l"(a), "l"(b));
}
__device__ __forceinline__ unsigned long long f2_to_u64(float2 f) {
    unsigned long long r;
    asm("mov.b64 %0, {%1, %2};" : "=l"(r) : "f"(f.x), "f"(f.y));
    return r;
}
__device__ __forceinline__ void unpack2(unsigned long long v, float& lo, float& hi) {
    asm("mov.b64 {%0, %1}, %2;" : "=f"(lo), "=f"(hi) : "l"(v));
}

// Accumulate 8 fp16 channels (one uint4 corner load) into 4 packed f32x2 accs.
__device__ __forceinline__ void accum8(unsigned long long& acc0,
                                       unsigned long long& acc1,
                                       unsigned long long& acc2,
                                       unsigned long long& acc3,
                                       const uint4& u,
                                       unsigned long long wgt) {
    fma2(acc0, wgt, f2_to_u64(__half22float2(*(const __half2*)&u.x)));
    fma2(acc1, wgt, f2_to_u64(__half22float2(*(const __half2*)&u.y)));
    fma2(acc2, wgt, f2_to_u64(__half22float2(*(const __half2*)&u.z)));
    fma2(acc3, wgt, f2_to_u64(__half22float2(*(const __half2*)&u.w)));
}

// ---------------------------------------------------------------------------
// Pool: block = (32, 4) = 4 bins, ONE WARP PER BIN; thread t -> channels 8t..8t+7.
// Branch-free hot path: all 64 corner LDG.128 issued unconditionally.
// ---------------------------------------------------------------------------
__global__ void __launch_bounds__(128, 8) pool_kernel(
    const float* __restrict__ rois,
    const float* __restrict__ offset,
    float* __restrict__ out)
{
    const int bin = blockIdx.x * 4 + threadIdx.y;  // 0..51
    if (bin >= PQ * PQ) return;
    const int n   = blockIdx.y;                    // 0..127
    const int ph  = bin / PQ;
    const int pw  = bin - ph * PQ;
    const int t   = threadIdx.x;                   // 0..31

    // --- geometry (replicates reference IEEE f32 ops) ---
    const float* r = rois + n * 5;
    const int   b  = (int)__ldg(&r[0]);
    const float rsw = rintf(__ldg(&r[1])) * SPATIAL_SCALE - 0.5f;
    const float rsh = rintf(__ldg(&r[2])) * SPATIAL_SCALE - 0.5f;
    const float rew = (rintf(__ldg(&r[3])) + 1.0f) * SPATIAL_SCALE - 0.5f;
    const float reh = (rintf(__ldg(&r[4])) + 1.0f) * SPATIAL_SCALE - 0.5f;
    const float rw = fmaxf(rew - rsw, 0.1f);
    const float rh = fmaxf(reh - rsh, 0.1f);
    const float binw = rw / (float)PQ;
    const float binh = rh / (float)PQ;
    const float subw = binw / (float)SQ;
    const float subh = binh / (float)SQ;

    const int part_h = (int)floorf((float)ph / (float)PQ * (float)PQ);
    const int part_w = (int)floorf((float)pw / (float)PQ * (float)PQ);

    const float tx_off = __ldg(&offset[n * (2 * PQ * PQ) + part_h * PQ + part_w]) * TRANS_STD;
    const float ty_off = __ldg(&offset[n * (2 * PQ * PQ) + PQ * PQ + part_h * PQ + part_w]) * TRANS_STD;

    const float wstart = (float)pw * binw + rsw + tx_off * rw;
    const float hstart = (float)ph * binh + rsh + ty_off * rh;

    // --- per-sample separable weights & offsets (branch-free, packed) ---
    unsigned long long wy0p[SQ], wy1p[SQ], wx0p[SQ], wx1p[SQ];
    int ro0[SQ], ro1[SQ], co0[SQ], co1[SQ];
    float nvh = 0.f, nvw = 0.f;

    #pragma unroll
    for (int ih = 0; ih < SQ; ih++) {
        const float h  = hstart + (float)ih * subh;
        const bool  vh = (h >= -0.5f) && (h <= (float)HQ - 0.5f);
        nvh += vh ? 1.f : 0.f;
        const float hc  = fminf(fmaxf(h, 0.f), (float)(HQ - 1));
        const float y0f = floorf(hc);
        const float dy  = hc - y0f;
        const int y0 = (int)y0f;
        wy0p[ih] = pack2(vh ? (1.f - dy) : 0.f);
        wy1p[ih] = pack2(vh ? dy : 0.f);
        ro0[ih] = y0 * (WQ * CQ);
        ro1[ih] = min(y0 + 1, HQ - 1) * (WQ * CQ);
    }
    #pragma unroll
    for (int iw = 0; iw < SQ; iw++) {
        const float w  = wstart + (float)iw * subw;
        const bool  vw = (w >= -0.5f) && (w <= (float)WQ - 0.5f);
        nvw += vw ? 1.f : 0.f;
        const float wc  = fminf(fmaxf(w, 0.f), (float)(WQ - 1));
        const float x0f = floorf(wc);
        const float dx  = wc - x0f;
        const int x0 = (int)x0f;
        wx0p[iw] = pack2(vw ? (1.f - dx) : 0.f);
        wx1p[iw] = pack2(vw ? dx : 0.f);
        co0[iw] = x0 * CQ;
        co1[iw] = min(x0 + 1, WQ - 1) * CQ;
    }

    const __half* base = g_tdata + (size_t)b * HQ * WQ * CQ + 8 * t;

    unsigned long long acc0 = 0ull, acc1 = 0ull, acc2 = 0ull, acc3 = 0ull;

    #pragma unroll
    for (int ih = 0; ih < SQ; ih++) {
        #pragma unroll
        for (int iw = 0; iw < SQ; iw++) {
            // packed weights: 1 FMUL2 each
            const unsigned long long w00 = mul2(wy0p[ih], wx0p[iw]);
            const unsigned long long w01 = mul2(wy0p[ih], wx1p[iw]);
            const unsigned long long w10 = mul2(wy1p[ih], wx0p[iw]);
            const unsigned long long w11 = mul2(wy1p[ih], wx1p[iw]);

            // 4 corner LDG.128 (8 fp16 channels each), independent
            const uint4 u00 = __ldg((const uint4*)(base + ro0[ih] + co0[iw]));
            const uint4 u01 = __ldg((const uint4*)(base + ro0[ih] + co1[iw]));
            const uint4 u10 = __ldg((const uint4*)(base + ro1[ih] + co0[iw]));
            const uint4 u11 = __ldg((const uint4*)(base + ro1[ih] + co1[iw]));

            accum8(acc0, acc1, acc2, acc3, u00, w00);
            accum8(acc0, acc1, acc2, acc3, u01, w01);
            accum8(acc0, acc1, acc2, acc3, u10, w10);
            accum8(acc0, acc1, acc2, acc3, u11, w11);
        }
    }

    const float count = nvh * nvw;
    float a[8];
    unpack2(acc0, a[0], a[1]);
    unpack2(acc1, a[2], a[3]);
    unpack2(acc2, a[4], a[5]);
    unpack2(acc3, a[6], a[7]);

    float res[8];
    if (count > 0.f) {
        #pragma unroll
        for (int k = 0; k < 8; k++) res[k] = a[k] / count;
    } else {
        #pragma unroll
        for (int k = 0; k < 8; k++) res[k] = 0.f;
    }

    // out layout (N, C, 7, 7): channel stride = 49
    float* o = out + ((size_t)n * CQ + 8 * t) * (PQ * PQ) + bin;
    #pragma unroll
    for (int k = 0; k < 8; k++) o[k * PQ * PQ] = res[k];
}

extern "C" void kernel_launch(void* const* d_in, const int* in_sizes, int n_in,
                              void* d_out, int out_size) {
    const float* data   = (const float*)d_in[0];
    const float* rois   = (const float*)d_in[1];
    const float* offset = (const float*)d_in[2];
    float* out = (float*)d_out;

    dim3 tg(HQ * WQ / 64, CQ / 32, BQ);     // (256, 8, 2)
    transpose_kernel<<<tg, 256>>>(data);

    dim3 pg((PQ * PQ + 3) / 4, NROI);       // (13, 128)
    dim3 pb(32, 4);
    pool_kernel<<<pg, pb>>>(rois, offset, out);
}

// round 9
// speedup vs baseline: 1.0010x; 1.0010x over previous
#include <cuda_runtime.h>
#include <cuda_fp16.h>
#include <cstdint>

// ---------------------------------------------------------------------------
// DeformRoIPooling (deformable PS-RoI pooling), GROUP_SIZE=1 specialization.
//
// data:   (B=2, C=256, H=128, W=128) f32
// rois:   (N=128, 5) f32  [b, x1, y1, x2, y2]
// offset: (N=128, 2, 7, 7) f32
// out:    (N=128, 256, 7, 7) f32
//
// R9: fp16 scratch + branch-free flat gather (R6 shape: 64 thr/bin, 4 ch/thr)
//     with per-bin sample tables (corner offsets + packed f32x2 weights)
//     precomputed into SMEM by 16 threads -> ~45 regs, 62% occupancy,
//     4x smaller preamble.
// ---------------------------------------------------------------------------

#define BQ   2
#define CQ   256
#define HQ   128
#define WQ   128
#define NROI 128
#define PQ   7
#define SQ   4
#define SPATIAL_SCALE 0.0625f
#define TRANS_STD 0.1f

// 16 MB transposed fp16 scratch: (B, H, W, C) — L2-resident
__device__ __half g_tdata[(size_t)BQ * HQ * WQ * CQ];

// ---------------------------------------------------------------------------
// Transpose + f32->fp16 convert: per batch, (C=256) x (P=16384) -> (P) x (C).
// ---------------------------------------------------------------------------
__global__ void __launch_bounds__(256) transpose_kernel(const float* __restrict__ src) {
    __shared__ float tile[32][68];
    const int b  = blockIdx.z;
    const int c0 = blockIdx.y * 32;
    const int p0 = blockIdx.x * 64;
    const float* s = src + ((size_t)b * CQ + c0) * (HQ * WQ) + p0;
    __half* d      = g_tdata + (size_t)b * HQ * WQ * CQ;

    const int i = threadIdx.x;
    {
        const int c = i >> 4;
        const int q = i & 15;
        #pragma unroll
        for (int r = 0; r < 2; r++) {
            float4 v = *(const float4*)(s + (size_t)(c + 16 * r) * (HQ * WQ) + 4 * q);
            *(float4*)&tile[c + 16 * r][4 * q] = v;
        }
    }
    __syncthreads();
    {
        const int p = i >> 2;               // 0..63
        const int q = i & 3;                // 0..3 -> channel group of 8
        __half2 h[4];
        #pragma unroll
        for (int k = 0; k < 4; k++) {
            float2 f;
            f.x = tile[q * 8 + 2 * k + 0][p];
            f.y = tile[q * 8 + 2 * k + 1][p];
            h[k] = __float22half2_rn(f);
        }
        *(uint4*)(d + (size_t)(p0 + p) * CQ + c0 + 8 * q) = *(const uint4*)h;
    }
}

// ---------------------------------------------------------------------------
// Packed f32x2 helpers (Blackwell FFMA2 via PTX)
// ---------------------------------------------------------------------------
__device__ __forceinline__ void fma2(unsigned long long& d,
                                     unsigned long long a,
                                     unsigned long long b) {
    asm("fma.rn.f32x2 %0, %1, %2, %0;" : "+l"(d) : "l"(a), "l"(b));
}
__device__ __forceinline__ unsigned long long f2_to_u64(float2 f) {
    unsigned long long r;
    asm("mov.b64 %0, {%1, %2};" : "=l"(r) : "f"(f.x), "f"(f.y));
    return r;
}
__device__ __forceinline__ void unpack2(unsigned long long v, float& lo, float& hi) {
    asm("mov.b64 {%0, %1}, %2;" : "=f"(lo), "=f"(hi) : "l"(v));
}

// ---------------------------------------------------------------------------
// Pool: block = (64, 4) = 4 bins x 64 threads; thread t -> channels 4t..4t+3.
// Per-bin tables in SMEM: for each of 16 samples, 4 corner element offsets
// (int4) + 4 duplicated-packed f32x2 weights. 12 floats / sample.
// ---------------------------------------------------------------------------
__global__ void __launch_bounds__(256, 5) pool_kernel(
    const float* __restrict__ rois,
    const float* __restrict__ offset,
    float* __restrict__ out)
{
    __shared__ float stab[4][16][12];   // [bin-slot][sample][offs int4 | 4x f32x2 weights]
    __shared__ float scount[4];

    const int slot = threadIdx.y;                        // 0..3
    const int bin  = min(blockIdx.x * 4 + slot, PQ * PQ - 1);  // clamp: 49..51 -> 48
    const int n    = blockIdx.y;                         // 0..127
    const int ph   = bin / PQ;
    const int pw   = bin - ph * PQ;
    const int t    = threadIdx.x;                        // 0..63

    const int bidx = (int)__ldg(&rois[n * 5 + 0]);       // batch (uniform)

    // ---- precompute per-bin tables: 16 threads, one per sample ----
    if (t < 16) {
        const int s  = t;
        const int ih = s >> 2;
        const int iw = s & 3;

        // geometry (replicates reference IEEE f32 ops)
        const float* r = rois + n * 5;
        const float rsw = rintf(__ldg(&r[1])) * SPATIAL_SCALE - 0.5f;
        const float rsh = rintf(__ldg(&r[2])) * SPATIAL_SCALE - 0.5f;
        const float rew = (rintf(__ldg(&r[3])) + 1.0f) * SPATIAL_SCALE - 0.5f;
        const float reh = (rintf(__ldg(&r[4])) + 1.0f) * SPATIAL_SCALE - 0.5f;
        const float rw = fmaxf(rew - rsw, 0.1f);
        const float rh = fmaxf(reh - rsh, 0.1f);
        const float binw = rw / (float)PQ;
        const float binh = rh / (float)PQ;
        const float subw = binw / (float)SQ;
        const float subh = binh / (float)SQ;

        const int part_h = (int)floorf((float)ph / (float)PQ * (float)PQ);
        const int part_w = (int)floorf((float)pw / (float)PQ * (float)PQ);

        const float tx_off = __ldg(&offset[n * (2 * PQ * PQ) + part_h * PQ + part_w]) * TRANS_STD;
        const float ty_off = __ldg(&offset[n * (2 * PQ * PQ) + PQ * PQ + part_h * PQ + part_w]) * TRANS_STD;

        const float wstart = (float)pw * binw + rsw + tx_off * rw;
        const float hstart = (float)ph * binh + rsh + ty_off * rh;

        // this sample's position
        const float h  = hstart + (float)ih * subh;
        const float w  = wstart + (float)iw * subw;
        const bool  vh = (h >= -0.5f) && (h <= (float)HQ - 0.5f);
        const bool  vw = (w >= -0.5f) && (w <= (float)WQ - 0.5f);
        const bool  valid = vh && vw;

        const float hc  = fminf(fmaxf(h, 0.f), (float)(HQ - 1));
        const float wc  = fminf(fmaxf(w, 0.f), (float)(WQ - 1));
        const float y0f = floorf(hc);
        const float x0f = floorf(wc);
        const float dy  = hc - y0f;
        const float dx  = wc - x0f;
        const int y0 = (int)y0f;
        const int x0 = (int)x0f;
        const int y1 = min(y0 + 1, HQ - 1);
        const int x1 = min(x0 + 1, WQ - 1);

        const float w00 = valid ? (1.f - dy) * (1.f - dx) : 0.f;
        const float w01 = valid ? (1.f - dy) * dx         : 0.f;
        const float w10 = valid ? dy * (1.f - dx)         : 0.f;
        const float w11 = valid ? dy * dx                 : 0.f;

        float* sp = &stab[slot][s][0];
        *(int4*)sp = make_int4(y0 * (WQ * CQ) + x0 * CQ,
                               y0 * (WQ * CQ) + x1 * CQ,
                               y1 * (WQ * CQ) + x0 * CQ,
                               y1 * (WQ * CQ) + x1 * CQ);
        ((float2*)sp)[2] = make_float2(w00, w00);
        ((float2*)sp)[3] = make_float2(w01, w01);
        ((float2*)sp)[4] = make_float2(w10, w10);
        ((float2*)sp)[5] = make_float2(w11, w11);

        if (s == 0) {
            // count = (#valid rows) * (#valid cols)
            float nvh = 0.f, nvw = 0.f;
            #pragma unroll
            for (int k = 0; k < SQ; k++) {
                const float hh = hstart + (float)k * subh;
                const float ww = wstart + (float)k * subw;
                nvh += ((hh >= -0.5f) && (hh <= (float)HQ - 0.5f)) ? 1.f : 0.f;
                nvw += ((ww >= -0.5f) && (ww <= (float)WQ - 0.5f)) ? 1.f : 0.f;
            }
            scount[slot] = nvh * nvw;
        }
    }
    __syncthreads();

    // ---- hot loop: branch-free flat gather over 16 samples x 4 corners ----
    const __half* base = g_tdata + (size_t)bidx * HQ * WQ * CQ + 4 * t;

    unsigned long long acc01 = 0ull, acc23 = 0ull;

    #pragma unroll
    for (int s = 0; s < 16; s++) {
        const float* sp = &stab[slot][s][0];
        const int4 o = *(const int4*)sp;                            // LDS.128 (broadcast)
        const ulonglong2 wA = *(const ulonglong2*)(sp + 4);         // w00, w01 packed
        const ulonglong2 wB = *(const ulonglong2*)(sp + 8);         // w10, w11 packed

        const uint2 u00 = __ldg((const uint2*)(base + o.x));
        const uint2 u01 = __ldg((const uint2*)(base + o.y));
        const uint2 u10 = __ldg((const uint2*)(base + o.z));
        const uint2 u11 = __ldg((const uint2*)(base + o.w));

        fma2(acc01, wA.x, f2_to_u64(__half22float2(*(const __half2*)&u00.x)));
        fma2(acc23, wA.x, f2_to_u64(__half22float2(*(const __half2*)&u00.y)));
        fma2(acc01, wA.y, f2_to_u64(__half22float2(*(const __half2*)&u01.x)));
        fma2(acc23, wA.y, f2_to_u64(__half22float2(*(const __half2*)&u01.y)));
        fma2(acc01, wB.x, f2_to_u64(__half22float2(*(const __half2*)&u10.x)));
        fma2(acc23, wB.x, f2_to_u64(__half22float2(*(const __half2*)&u10.y)));
        fma2(acc01, wB.y, f2_to_u64(__half22float2(*(const __half2*)&u11.x)));
        fma2(acc23, wB.y, f2_to_u64(__half22float2(*(const __half2*)&u11.y)));
    }

    const float count = scount[slot];
    float a0, a1, a2, a3;
    unpack2(acc01, a0, a1);
    unpack2(acc23, a2, a3);

    float r0, r1, r2, r3;
    if (count > 0.f) {
        r0 = a0 / count; r1 = a1 / count; r2 = a2 / count; r3 = a3 / count;
    } else {
        r0 = r1 = r2 = r3 = 0.f;
    }

    // out layout (N, C, 7, 7): channel stride = 49. Clamped bins (49..51 -> 48)
    // write identical values as the true bin-48 owner: benign.
    float* o = out + ((size_t)n * CQ + 4 * t) * (PQ * PQ) + bin;
    o[0]            = r0;
    o[PQ * PQ]      = r1;
    o[2 * PQ * PQ]  = r2;
    o[3 * PQ * PQ]  = r3;
}

extern "C" void kernel_launch(void* const* d_in, const int* in_sizes, int n_in,
                              void* d_out, int out_size) {
    const float* data   = (const float*)d_in[0];
    const float* rois   = (const float*)d_in[1];
    const float* offset = (const float*)d_in[2];
    float* out = (float*)d_out;

    dim3 tg(HQ * WQ / 64, CQ / 32, BQ);     // (256, 8, 2)
    transpose_kernel<<<tg, 256>>>(data);

    dim3 pg((PQ * PQ + 3) / 4, NROI);       // (13, 128)
    dim3 pb(64, 4);
    pool_kernel<<<pg, pb>>>(rois, offset, out);
}

// round 10
// speedup vs baseline: 1.0634x; 1.0624x over previous
#include <cuda_runtime.h>
#include <cuda_fp16.h>
#include <cstdint>

// ---------------------------------------------------------------------------
// DeformRoIPooling (deformable PS-RoI pooling), GROUP_SIZE=1 specialization.
//
// data:   (B=2, C=256, H=128, W=128) f32
// rois:   (N=128, 5) f32  [b, x1, y1, x2, y2]
// offset: (N=128, 2, 7, 7) f32
// out:    (N=128, 256, 7, 7) f32
//
// R10: fp16 scratch; one warp per bin, 8 channels/thread (LDG.128 corners);
//      per-bin SMEM sample tables (offsets + fp16 weights); 4-corner
//      interpolation in HFMA2, single convert per sample, f32x2 accumulation.
// ---------------------------------------------------------------------------

#define BQ   2
#define CQ   256
#define HQ   128
#define WQ   128
#define NROI 128
#define PQ   7
#define SQ   4
#define SPATIAL_SCALE 0.0625f
#define TRANS_STD 0.1f

// 16 MB transposed fp16 scratch: (B, H, W, C) — L2-resident
__device__ __half g_tdata[(size_t)BQ * HQ * WQ * CQ];

// ---------------------------------------------------------------------------
// Transpose + f32->fp16 convert: per batch, (C=256) x (P=16384) -> (P) x (C).
// ---------------------------------------------------------------------------
__global__ void __launch_bounds__(256) transpose_kernel(const float* __restrict__ src) {
    __shared__ float tile[32][68];
    const int b  = blockIdx.z;
    const int c0 = blockIdx.y * 32;
    const int p0 = blockIdx.x * 64;
    const float* s = src + ((size_t)b * CQ + c0) * (HQ * WQ) + p0;
    __half* d      = g_tdata + (size_t)b * HQ * WQ * CQ;

    const int i = threadIdx.x;
    {
        const int c = i >> 4;
        const int q = i & 15;
        #pragma unroll
        for (int r = 0; r < 2; r++) {
            float4 v = *(const float4*)(s + (size_t)(c + 16 * r) * (HQ * WQ) + 4 * q);
            *(float4*)&tile[c + 16 * r][4 * q] = v;
        }
    }
    __syncthreads();
    {
        const int p = i >> 2;               // 0..63
        const int q = i & 3;                // 0..3 -> channel group of 8
        __half2 h[4];
        #pragma unroll
        for (int k = 0; k < 4; k++) {
            float2 f;
            f.x = tile[q * 8 + 2 * k + 0][p];
            f.y = tile[q * 8 + 2 * k + 1][p];
            h[k] = __float22half2_rn(f);
        }
        *(uint4*)(d + (size_t)(p0 + p) * CQ + c0 + 8 * q) = *(const uint4*)h;
    }
}

// ---------------------------------------------------------------------------
// Packed f32x2 helpers
// ---------------------------------------------------------------------------
__device__ __forceinline__ void add2(unsigned long long& d, unsigned long long a) {
    asm("add.rn.f32x2 %0, %0, %1;" : "+l"(d) : "l"(a));
}
__device__ __forceinline__ unsigned long long f2_to_u64(float2 f) {
    unsigned long long r;
    asm("mov.b64 %0, {%1, %2};" : "=l"(r) : "f"(f.x), "f"(f.y));
    return r;
}
__device__ __forceinline__ void unpack2(unsigned long long v, float& lo, float& hi) {
    asm("mov.b64 {%0, %1}, %2;" : "=f"(lo), "=f"(hi) : "l"(v));
}

// Per-sample record in shared memory (32B: int4 offsets + 4 duplicated half2 weights)
struct __align__(16) SampleRec {
    int4    o;                     // element offsets of the 4 corners
    __half2 w00, w01, w10, w11;    // duplicated fp16 bilinear weights
};

// ---------------------------------------------------------------------------
// Pool: block = (32, 7) = 7 bins x 1 warp; thread t -> channels 8t..8t+7.
// ---------------------------------------------------------------------------
__global__ void __launch_bounds__(224, 5) pool_kernel(
    const float* __restrict__ rois,
    const float* __restrict__ offset,
    float* __restrict__ out)
{
    __shared__ SampleRec stab[PQ][16];
    __shared__ float scount[PQ];

    const int slot = threadIdx.y;                  // 0..6
    const int bin  = blockIdx.x * PQ + slot;       // 0..48 exact
    const int n    = blockIdx.y;                   // 0..127
    const int ph   = bin / PQ;
    const int pw   = bin - ph * PQ;
    const int t    = threadIdx.x;                  // 0..31

    const int bidx = (int)__ldg(&rois[n * 5 + 0]); // batch (uniform)

    // ---- per-bin table build: 16 threads, one per sample ----
    if (t < 16) {
        const int s  = t;
        const int ih = s >> 2;
        const int iw = s & 3;

        // geometry (replicates reference IEEE f32 ops)
        const float* r = rois + n * 5;
        const float rsw = rintf(__ldg(&r[1])) * SPATIAL_SCALE - 0.5f;
        const float rsh = rintf(__ldg(&r[2])) * SPATIAL_SCALE - 0.5f;
        const float rew = (rintf(__ldg(&r[3])) + 1.0f) * SPATIAL_SCALE - 0.5f;
        const float reh = (rintf(__ldg(&r[4])) + 1.0f) * SPATIAL_SCALE - 0.5f;
        const float rw = fmaxf(rew - rsw, 0.1f);
        const float rh = fmaxf(reh - rsh, 0.1f);
        const float binw = rw / (float)PQ;
        const float binh = rh / (float)PQ;
        const float subw = binw / (float)SQ;
        const float subh = binh / (float)SQ;

        const int part_h = (int)floorf((float)ph / (float)PQ * (float)PQ);
        const int part_w = (int)floorf((float)pw / (float)PQ * (float)PQ);

        const float tx_off = __ldg(&offset[n * (2 * PQ * PQ) + part_h * PQ + part_w]) * TRANS_STD;
        const float ty_off = __ldg(&offset[n * (2 * PQ * PQ) + PQ * PQ + part_h * PQ + part_w]) * TRANS_STD;

        const float wstart = (float)pw * binw + rsw + tx_off * rw;
        const float hstart = (float)ph * binh + rsh + ty_off * rh;

        const float h  = hstart + (float)ih * subh;
        const float w  = wstart + (float)iw * subw;
        const bool  vh = (h >= -0.5f) && (h <= (float)HQ - 0.5f);
        const bool  vw = (w >= -0.5f) && (w <= (float)WQ - 0.5f);
        const bool  valid = vh && vw;

        const float hc  = fminf(fmaxf(h, 0.f), (float)(HQ - 1));
        const float wc  = fminf(fmaxf(w, 0.f), (float)(WQ - 1));
        const float y0f = floorf(hc);
        const float x0f = floorf(wc);
        const float dy  = hc - y0f;
        const float dx  = wc - x0f;
        const int y0 = (int)y0f;
        const int x0 = (int)x0f;
        const int y1 = min(y0 + 1, HQ - 1);
        const int x1 = min(x0 + 1, WQ - 1);

        const float w00 = valid ? (1.f - dy) * (1.f - dx) : 0.f;
        const float w01 = valid ? (1.f - dy) * dx         : 0.f;
        const float w10 = valid ? dy * (1.f - dx)         : 0.f;
        const float w11 = valid ? dy * dx                 : 0.f;

        SampleRec rec;
        rec.o = make_int4(y0 * (WQ * CQ) + x0 * CQ,
                          y0 * (WQ * CQ) + x1 * CQ,
                          y1 * (WQ * CQ) + x0 * CQ,
                          y1 * (WQ * CQ) + x1 * CQ);
        rec.w00 = __float2half2_rn(w00);
        rec.w01 = __float2half2_rn(w01);
        rec.w10 = __float2half2_rn(w10);
        rec.w11 = __float2half2_rn(w11);
        stab[slot][s] = rec;

        if (s == 0) {
            float nvh = 0.f, nvw = 0.f;
            #pragma unroll
            for (int k = 0; k < SQ; k++) {
                const float hh = hstart + (float)k * subh;
                const float ww = wstart + (float)k * subw;
                nvh += ((hh >= -0.5f) && (hh <= (float)HQ - 0.5f)) ? 1.f : 0.f;
                nvw += ((ww >= -0.5f) && (ww <= (float)WQ - 0.5f)) ? 1.f : 0.f;
            }
            scount[slot] = nvh * nvw;
        }
    }
    __syncthreads();

    // ---- hot loop: 16 samples; HFMA2 corner interp, f32x2 accumulation ----
    const __half* base = g_tdata + (size_t)bidx * HQ * WQ * CQ + 8 * t;

    unsigned long long acc0 = 0ull, acc1 = 0ull, acc2 = 0ull, acc3 = 0ull;

    #pragma unroll
    for (int s = 0; s < 16; s++) {
        const SampleRec rec = stab[slot][s];

        const uint4 u00 = __ldg((const uint4*)(base + rec.o.x));
        const uint4 u01 = __ldg((const uint4*)(base + rec.o.y));
        const uint4 u10 = __ldg((const uint4*)(base + rec.o.z));
        const uint4 u11 = __ldg((const uint4*)(base + rec.o.w));

        const __half2* h00 = (const __half2*)&u00;
        const __half2* h01 = (const __half2*)&u01;
        const __half2* h10 = (const __half2*)&u10;
        const __half2* h11 = (const __half2*)&u11;

        __half2 s0 = __hmul2(rec.w00, h00[0]);
        __half2 s1 = __hmul2(rec.w00, h00[1]);
        __half2 s2 = __hmul2(rec.w00, h00[2]);
        __half2 s3 = __hmul2(rec.w00, h00[3]);
        s0 = __hfma2(rec.w01, h01[0], s0);
        s1 = __hfma2(rec.w01, h01[1], s1);
        s2 = __hfma2(rec.w01, h01[2], s2);
        s3 = __hfma2(rec.w01, h01[3], s3);
        s0 = __hfma2(rec.w10, h10[0], s0);
        s1 = __hfma2(rec.w10, h10[1], s1);
        s2 = __hfma2(rec.w10, h10[2], s2);
        s3 = __hfma2(rec.w10, h10[3], s3);
        s0 = __hfma2(rec.w11, h11[0], s0);
        s1 = __hfma2(rec.w11, h11[1], s1);
        s2 = __hfma2(rec.w11, h11[2], s2);
        s3 = __hfma2(rec.w11, h11[3], s3);

        add2(acc0, f2_to_u64(__half22float2(s0)));
        add2(acc1, f2_to_u64(__half22float2(s1)));
        add2(acc2, f2_to_u64(__half22float2(s2)));
        add2(acc3, f2_to_u64(__half22float2(s3)));
    }

    const float count = scount[slot];
    float a[8];
    unpack2(acc0, a[0], a[1]);
    unpack2(acc1, a[2], a[3]);
    unpack2(acc2, a[4], a[5]);
    unpack2(acc3, a[6], a[7]);

    float res[8];
    if (count > 0.f) {
        #pragma unroll
        for (int k = 0; k < 8; k++) res[k] = a[k] / count;
    } else {
        #pragma unroll
        for (int k = 0; k < 8; k++) res[k] = 0.f;
    }

    // out layout (N, C, 7, 7): channel stride = 49
    float* o = out + ((size_t)n * CQ + 8 * t) * (PQ * PQ) + bin;
    #pragma unroll
    for (int k = 0; k < 8; k++) o[k * PQ * PQ] = res[k];
}

extern "C" void kernel_launch(void* const* d_in, const int* in_sizes, int n_in,
                              void* d_out, int out_size) {
    const float* data   = (const float*)d_in[0];
    const float* rois   = (const float*)d_in[1];
    const float* offset = (const float*)d_in[2];
    float* out = (float*)d_out;

    dim3 tg(HQ * WQ / 64, CQ / 32, BQ);     // (256, 8, 2)
    transpose_kernel<<<tg, 256>>>(data);

    dim3 pg(PQ, NROI);                      // (7, 128)
    dim3 pb(32, PQ);
    pool_kernel<<<pg, pb>>>(rois, offset, out);
}

// round 12
// speedup vs baseline: 1.2279x; 1.1547x over previous
#include <cuda_runtime.h>
#include <cuda_fp16.h>
#include <cstdint>

// ---------------------------------------------------------------------------
// DeformRoIPooling (deformable PS-RoI pooling), GROUP_SIZE=1 specialization.
//
// data:   (B=2, C=256, H=128, W=128) f32
// rois:   (N=128, 5) f32  [b, x1, y1, x2, y2]
// offset: (N=128, 2, 7, 7) f32
// out:    (N=128, 256, 7, 7) f32
//
// R11b: R10 gather (fp16 scratch, 1 warp/bin, LDG.128 corners, HFMA2 interp,
//       f32x2 accumulate) + SMEM-staged coalesced output stores (block = one
//       ph-row of 7 bins) + reciprocal-multiply epilogue.
//       Fix vs R11: 16B-align the staging buffer (it followed a 28B array,
//       so float4 STS trapped with misaligned address).
// ---------------------------------------------------------------------------

#define BQ   2
#define CQ   256
#define HQ   128
#define WQ   128
#define NROI 128
#define PQ   7
#define SQ   4
#define SPATIAL_SCALE 0.0625f
#define TRANS_STD 0.1f

// 16 MB transposed fp16 scratch: (B, H, W, C) — L2-resident
__device__ __half g_tdata[(size_t)BQ * HQ * WQ * CQ];

// ---------------------------------------------------------------------------
// Transpose + f32->fp16 convert: per batch, (C=256) x (P=16384) -> (P) x (C).
// ---------------------------------------------------------------------------
__global__ void __launch_bounds__(256) transpose_kernel(const float* __restrict__ src) {
    __shared__ float tile[32][68];
    const int b  = blockIdx.z;
    const int c0 = blockIdx.y * 32;
    const int p0 = blockIdx.x * 64;
    const float* s = src + ((size_t)b * CQ + c0) * (HQ * WQ) + p0;
    __half* d      = g_tdata + (size_t)b * HQ * WQ * CQ;

    const int i = threadIdx.x;
    {
        const int c = i >> 4;
        const int q = i & 15;
        #pragma unroll
        for (int r = 0; r < 2; r++) {
            float4 v = *(const float4*)(s + (size_t)(c + 16 * r) * (HQ * WQ) + 4 * q);
            *(float4*)&tile[c + 16 * r][4 * q] = v;
        }
    }
    __syncthreads();
    {
        const int p = i >> 2;               // 0..63
        const int q = i & 3;                // 0..3 -> channel group of 8
        __half2 h[4];
        #pragma unroll
        for (int k = 0; k < 4; k++) {
            float2 f;
            f.x = tile[q * 8 + 2 * k + 0][p];
            f.y = tile[q * 8 + 2 * k + 1][p];
            h[k] = __float22half2_rn(f);
        }
        *(uint4*)(d + (size_t)(p0 + p) * CQ + c0 + 8 * q) = *(const uint4*)h;
    }
}

// ---------------------------------------------------------------------------
// Packed f32x2 helpers
// ---------------------------------------------------------------------------
__device__ __forceinline__ void add2(unsigned long long& d, unsigned long long a) {
    asm("add.rn.f32x2 %0, %0, %1;" : "+l"(d) : "l"(a));
}
__device__ __forceinline__ unsigned long long f2_to_u64(float2 f) {
    unsigned long long r;
    asm("mov.b64 %0, {%1, %2};" : "=l"(r) : "f"(f.x), "f"(f.y));
    return r;
}
__device__ __forceinline__ void unpack2(unsigned long long v, float& lo, float& hi) {
    asm("mov.b64 {%0, %1}, %2;" : "=f"(lo), "=f"(hi) : "l"(v));
}

// Per-sample record in shared memory (32B: int4 offsets + 4 duplicated half2 weights)
struct __align__(16) SampleRec {
    int4    o;                     // element offsets of the 4 corners
    __half2 w00, w01, w10, w11;    // duplicated fp16 bilinear weights
};

// ---------------------------------------------------------------------------
// Pool: block = (32, 7): blockIdx.x = ph, threadIdx.y = pw. One warp per bin.
// Thread t -> channels 8t..8t+7. Results staged in SMEM, written coalesced.
// ---------------------------------------------------------------------------
__global__ void __launch_bounds__(224, 5) pool_kernel(
    const float* __restrict__ rois,
    const float* __restrict__ offset,
    float* __restrict__ out)
{
    __shared__ __align__(16) float st[PQ][260];   // [pw][channel], padded row
    __shared__ SampleRec stab[PQ][16];
    __shared__ float scount[8];                   // padded to keep 16B alignment after

    const int pw = threadIdx.y;            // 0..6
    const int ph = blockIdx.x;             // 0..6
    const int n  = blockIdx.y;             // 0..127
    const int t  = threadIdx.x;            // 0..31

    const int bidx = (int)__ldg(&rois[n * 5 + 0]); // batch (uniform)

    // ---- per-bin table build: 16 lanes, one per sample (warp-private) ----
    if (t < 16) {
        const int s  = t;
        const int ih = s >> 2;
        const int iw = s & 3;

        // geometry (replicates reference IEEE f32 ops)
        const float* r = rois + n * 5;
        const float rsw = rintf(__ldg(&r[1])) * SPATIAL_SCALE - 0.5f;
        const float rsh = rintf(__ldg(&r[2])) * SPATIAL_SCALE - 0.5f;
        const float rew = (rintf(__ldg(&r[3])) + 1.0f) * SPATIAL_SCALE - 0.5f;
        const float reh = (rintf(__ldg(&r[4])) + 1.0f) * SPATIAL_SCALE - 0.5f;
        const float rw = fmaxf(rew - rsw, 0.1f);
        const float rh = fmaxf(reh - rsh, 0.1f);
        const float binw = rw / (float)PQ;
        const float binh = rh / (float)PQ;
        const float subw = binw / (float)SQ;
        const float subh = binh / (float)SQ;

        const int part_h = (int)floorf((float)ph / (float)PQ * (float)PQ);
        const int part_w = (int)floorf((float)pw / (float)PQ * (float)PQ);

        const float tx_off = __ldg(&offset[n * (2 * PQ * PQ) + part_h * PQ + part_w]) * TRANS_STD;
        const float ty_off = __ldg(&offset[n * (2 * PQ * PQ) + PQ * PQ + part_h * PQ + part_w]) * TRANS_STD;

        const float wstart = (float)pw * binw + rsw + tx_off * rw;
        const float hstart = (float)ph * binh + rsh + ty_off * rh;

        const float h  = hstart + (float)ih * subh;
        const float w  = wstart + (float)iw * subw;
        const bool  vh = (h >= -0.5f) && (h <= (float)HQ - 0.5f);
        const bool  vw = (w >= -0.5f) && (w <= (float)WQ - 0.5f);
        const bool  valid = vh && vw;

        const float hc  = fminf(fmaxf(h, 0.f), (float)(HQ - 1));
        const float wc  = fminf(fmaxf(w, 0.f), (float)(WQ - 1));
        const float y0f = floorf(hc);
        const float x0f = floorf(wc);
        const float dy  = hc - y0f;
        const float dx  = wc - x0f;
        const int y0 = (int)y0f;
        const int x0 = (int)x0f;
        const int y1 = min(y0 + 1, HQ - 1);
        const int x1 = min(x0 + 1, WQ - 1);

        const float w00 = valid ? (1.f - dy) * (1.f - dx) : 0.f;
        const float w01 = valid ? (1.f - dy) * dx         : 0.f;
        const float w10 = valid ? dy * (1.f - dx)         : 0.f;
        const float w11 = valid ? dy * dx                 : 0.f;

        SampleRec rec;
        rec.o = make_int4(y0 * (WQ * CQ) + x0 * CQ,
                          y0 * (WQ * CQ) + x1 * CQ,
                          y1 * (WQ * CQ) + x0 * CQ,
                          y1 * (WQ * CQ) + x1 * CQ);
        rec.w00 = __float2half2_rn(w00);
        rec.w01 = __float2half2_rn(w01);
        rec.w10 = __float2half2_rn(w10);
        rec.w11 = __float2half2_rn(w11);
        stab[pw][s] = rec;

        if (s == 0) {
            float nvh = 0.f, nvw = 0.f;
            #pragma unroll
            for (int k = 0; k < SQ; k++) {
                const float hh = hstart + (float)k * subh;
                const float ww = wstart + (float)k * subw;
                nvh += ((hh >= -0.5f) && (hh <= (float)HQ - 0.5f)) ? 1.f : 0.f;
                nvw += ((ww >= -0.5f) && (ww <= (float)WQ - 0.5f)) ? 1.f : 0.f;
            }
            scount[pw] = nvh * nvw;
        }
    }
    __syncwarp();   // table is warp-private

    // ---- hot loop: 16 samples; HFMA2 corner interp, f32x2 accumulation ----
    const __half* base = g_tdata + (size_t)bidx * HQ * WQ * CQ + 8 * t;

    unsigned long long acc0 = 0ull, acc1 = 0ull, acc2 = 0ull, acc3 = 0ull;

    #pragma unroll
    for (int s = 0; s < 16; s++) {
        const SampleRec rec = stab[pw][s];

        const uint4 u00 = __ldg((const uint4*)(base + rec.o.x));
        const uint4 u01 = __ldg((const uint4*)(base + rec.o.y));
        const uint4 u10 = __ldg((const uint4*)(base + rec.o.z));
        const uint4 u11 = __ldg((const uint4*)(base + rec.o.w));

        const __half2* h00 = (const __half2*)&u00;
        const __half2* h01 = (const __half2*)&u01;
        const __half2* h10 = (const __half2*)&u10;
        const __half2* h11 = (const __half2*)&u11;

        __half2 s0 = __hmul2(rec.w00, h00[0]);
        __half2 s1 = __hmul2(rec.w00, h00[1]);
        __half2 s2 = __hmul2(rec.w00, h00[2]);
        __half2 s3 = __hmul2(rec.w00, h00[3]);
        s0 = __hfma2(rec.w01, h01[0], s0);
        s1 = __hfma2(rec.w01, h01[1], s1);
        s2 = __hfma2(rec.w01, h01[2], s2);
        s3 = __hfma2(rec.w01, h01[3], s3);
        s0 = __hfma2(rec.w10, h10[0], s0);
        s1 = __hfma2(rec.w10, h10[1], s1);
        s2 = __hfma2(rec.w10, h10[2], s2);
        s3 = __hfma2(rec.w10, h10[3], s3);
        s0 = __hfma2(rec.w11, h11[0], s0);
        s1 = __hfma2(rec.w11, h11[1], s1);
        s2 = __hfma2(rec.w11, h11[2], s2);
        s3 = __hfma2(rec.w11, h11[3], s3);

        add2(acc0, f2_to_u64(__half22float2(s0)));
        add2(acc1, f2_to_u64(__half22float2(s1)));
        add2(acc2, f2_to_u64(__half22float2(s2)));
        add2(acc3, f2_to_u64(__half22float2(s3)));
    }

    // ---- epilogue: one reciprocal, 8 multiplies, stage into SMEM ----
    const float count = scount[pw];
    const float inv = (count > 0.f) ? (1.0f / count) : 0.f;

    float a[8];
    unpack2(acc0, a[0], a[1]);
    unpack2(acc1, a[2], a[3]);
    unpack2(acc2, a[4], a[5]);
    unpack2(acc3, a[6], a[7]);

    float4 lo = make_float4(a[0] * inv, a[1] * inv, a[2] * inv, a[3] * inv);
    float4 hi = make_float4(a[4] * inv, a[5] * inv, a[6] * inv, a[7] * inv);
    *(float4*)&st[pw][8 * t]     = lo;
    *(float4*)&st[pw][8 * t + 4] = hi;

    __syncthreads();

    // ---- coalesced write-out: 1792 values = 256 channels x 7 pw ----
    // Thread order follows output linear order (c major, pw minor) so each
    // warp's STG covers contiguous 28B runs instead of 32 scattered 4B.
    const int tid = pw * 32 + t;          // 0..223
    float* obase = out + (size_t)n * (CQ * PQ * PQ) + ph * PQ;
    #pragma unroll
    for (int i = 0; i < 8; i++) {
        const int f = tid + i * 224;      // 0..1791
        const int c  = f / PQ;
        const int p2 = f - c * PQ;
        obase[c * (PQ * PQ) + p2] = st[p2][c];
    }
}

extern "C" void kernel_launch(void* const* d_in, const int* in_sizes, int n_in,
                              void* d_out, int out_size) {
    const float* data   = (const float*)d_in[0];
    const float* rois   = (const float*)d_in[1];
    const float* offset = (const float*)d_in[2];
    float* out = (float*)d_out;

    dim3 tg(HQ * WQ / 64, CQ / 32, BQ);     // (256, 8, 2)
    transpose_kernel<<<tg, 256>>>(data);

    dim3 pg(PQ, NROI);                      // (ph, n)
    dim3 pb(32, PQ);
    pool_kernel<<<pg, pb>>>(rois, offset, out);
}